// round 16
// baseline (speedup 1.0000x reference)
#include <cuda_runtime.h>
#include <cstdint>
#include <cstddef>

#define B_   32
#define S_   2048
#define E_   1024
#define MTOT (B_ * S_)

// ---------------- scratch (no allocations allowed) ----------------
__device__ float g_scores[MTOT];
__device__ float g_attn[MTOT];
__device__ float g_q[B_ * E_];
__device__ float g_w1t[E_ * E_];   // w1 transposed [n][k], tf32-pre-rounded bits

// ---------------- helpers ----------------
__device__ __forceinline__ uint32_t f2tf32(float x) {
    uint32_t r;
    asm("cvt.rna.tf32.f32 %0, %1;" : "=r"(r) : "f"(x));
    return r;
}

__device__ __forceinline__ void mma_tf32(float d[4], const uint32_t a[4],
                                         const uint32_t b[2], const float c[4]) {
    asm volatile(
        "mma.sync.aligned.m16n8k8.row.col.f32.tf32.tf32.f32 "
        "{%0,%1,%2,%3},{%4,%5,%6,%7},{%8,%9},{%10,%11,%12,%13};\n"
        : "=f"(d[0]), "=f"(d[1]), "=f"(d[2]), "=f"(d[3])
        : "r"(a[0]), "r"(a[1]), "r"(a[2]), "r"(a[3]),
          "r"(b[0]), "r"(b[1]),
          "f"(c[0]), "f"(c[1]), "f"(c[2]), "f"(c[3]));
}

// ldmatrix x4: four 8x8 b16 matrices -> one reg each (tf32 fragment trick).
#define LDSM4(r0, r1, r2, r3, addr)                                          \
    asm volatile("ldmatrix.sync.aligned.m8n8.x4.shared.b16 {%0,%1,%2,%3}, [%4];" \
        : "=r"(r0), "=r"(r1), "=r"(r2), "=r"(r3) : "r"(addr))

__device__ __forceinline__ void cp16(uint32_t s, const void* g) {
    asm volatile("cp.async.cg.shared.global [%0],[%1],16;\n" :: "r"(s), "l"(g));
}
__device__ __forceinline__ void cp_commit() { asm volatile("cp.async.commit_group;\n"); }
template <int N>
__device__ __forceinline__ void cp_wait() { asm volatile("cp.async.wait_group %0;\n" ::"n"(N)); }

__device__ __forceinline__ float tanh_fast(float x) {
    float r;
    asm("tanh.approx.f32 %0, %1;" : "=f"(r) : "f"(x));
    return r;
}

// ---------------- kernel 1: init scratch + output ----------------
__global__ void init_kernel(const float* __restrict__ b1,
                            const float* __restrict__ b2,
                            float* __restrict__ out) {
    int i = blockIdx.x * blockDim.x + threadIdx.x;
    if (i < MTOT) g_scores[i] = 0.f;
    if (i < B_ * E_) {
        g_q[i] = b1[i & (E_ - 1)] + b2[i & (E_ - 1)];
        out[i] = 0.f;
    }
}

// ---------------- kernel 1b: transpose w1 -> g_w1t[n][k], tf32-rounded ----
__global__ void transpose_w1_kernel(const float* __restrict__ w1) {
    __shared__ float t[32][33];
    const int x = threadIdx.x, y = threadIdx.y;
    const int bx = blockIdx.x * 32, by = blockIdx.y * 32;
#pragma unroll
    for (int i = 0; i < 32; i += 8) t[y + i][x] = w1[(size_t)(by + y + i) * E_ + bx + x];
    __syncthreads();
#pragma unroll
    for (int i = 0; i < 32; i += 8)
        g_w1t[(size_t)(bx + y + i) * E_ + by + x] = __uint_as_float(f2tf32(t[x][y + i]));
}

// ---------------- kernel 2: q[b][e] += dec[b]·w2[:,e] ----------------
__global__ void qproj_kernel(const float* __restrict__ dec,
                             const float* __restrict__ w2) {
    __shared__ float sdec[32 * 128];
    const int tid = threadIdx.x;
    const int e   = blockIdx.x * 128 + tid;
    const int d0  = blockIdx.y * 128;

    for (int i = tid; i < 32 * 128; i += 128) {
        int b = i >> 7, d = i & 127;
        sdec[i] = dec[b * E_ + d0 + d];
    }
    __syncthreads();

    float acc[32];
#pragma unroll
    for (int b = 0; b < 32; b++) acc[b] = 0.f;
    for (int d = 0; d < 128; ++d) {
        float w = w2[(size_t)(d0 + d) * E_ + e];
#pragma unroll
        for (int b = 0; b < 32; b++) acc[b] += sdec[b * 128 + d] * w;
    }
#pragma unroll
    for (int b = 0; b < 32; b++) atomicAdd(&g_q[b * E_ + e], acc[b]);
}

// ---------------- kernel 3: score GEMM + tanh/v epilogue ----------------
// scores[m] += sum_n tanh( (enc@w1)[m,n] + q[b][n] ) * v[n]
// BM=128 BN=128 BK=32, 3-stage cp.async, 128 thr (4 warps 2x2),
// warp tile 64x64, ldmatrix, fragment double-buffering + cross-tile js0
// prefetch. STRICT race-free pipeline: each iter opens with cp_wait<0>
// (sole pending group = tile kt+1) + one __syncthreads that both
// publishes tile kt+1 and releases the stage being overwritten.
// A: raw fp32 (HW tf32 truncation); B: pre-rounded rna. 2 CTAs/SM.
#define BM   128
#define BN   128
#define BK   32
#define STAGES 3
#define KTILES (E_ / BK)
#define APAD 36
#define BNPAD 36
#define A_FLOATS (BM * APAD)               // 4608
#define B_FLOATS (BN * BNPAD)              // 4608
#define STAGE_FLOATS (A_FLOATS + B_FLOATS) // 9216
#define GEMM_SMEM (STAGES * STAGE_FLOATS * 4)   // 110592 B

__global__ __launch_bounds__(128, 2) void score_gemm_kernel(
    const float* __restrict__ enc, const float* __restrict__ v) {
    extern __shared__ float smem[];

    const int tid   = threadIdx.x;
    const int bn0   = blockIdx.x * BN;
    const int m0    = blockIdx.y * BM;
    const int batch = m0 / S_;   // BM divides S_

    const int warp = tid >> 5, lane = tid & 31;
    const int wm = warp >> 1, wn = warp & 1;   // 2x2 warp grid, 64x64 tiles
    const int g = lane >> 2, tg = lane & 3;
    const int q8 = lane >> 3, rr = lane & 7;   // ldmatrix lane mapping

    float cacc[4][8][4];
#pragma unroll
    for (int i = 0; i < 4; i++)
#pragma unroll
        for (int j = 0; j < 8; j++)
#pragma unroll
            for (int r = 0; r < 4; r++) cacc[i][j][r] = 0.f;

    const uint32_t smem_base = (uint32_t)__cvta_generic_to_shared(smem);
    // A matrices: rows {R+rr, R+8+rr} x k-halves {k0, k0+4}
    const uint32_t aOff = ((wm * 64 + (q8 & 1) * 8 + rr) * APAD + (q8 >> 1) * 4) * 4;
    // B matrices: n-rows {n0+rr, n0+8+rr} x k-halves {k0, k0+4}
    const uint32_t bOff = (uint32_t)(A_FLOATS * 4) +
                          ((wn * 64 + (q8 >> 1) * 8 + rr) * BNPAD + (q8 & 1) * 4) * 4;

    auto load_tile = [&](int kt, int s) {
        float* A  = smem + s * STAGE_FLOATS;
        float* Bn = A + A_FLOATS;          // layout [n][k], stride BNPAD
        const int kc = kt * BK;
#pragma unroll
        for (int i = 0; i < 8; i++) {      // A: 128 m-rows x 32 k floats
            int u = tid + 128 * i;
            int row = u >> 3, cu = (u & 7) << 2;
            cp16((uint32_t)__cvta_generic_to_shared(A + row * APAD + cu),
                 enc + (size_t)(m0 + row) * E_ + kc + cu);
        }
#pragma unroll
        for (int i = 0; i < 8; i++) {      // B: 128 n-rows x 32 k floats
            int u = tid + 128 * i;
            int row = u >> 3, cu = (u & 7) << 2;
            cp16((uint32_t)__cvta_generic_to_shared(Bn + row * BNPAD + cu),
                 g_w1t + (size_t)(bn0 + row) * E_ + kc + cu);
        }
    };

    uint32_t af[2][4][4], bf[2][8][2];
    auto lda = [&](uint32_t aAddr, int js, uint32_t f[4][4]) {
        const uint32_t a0 = aAddr + js * 32;
#pragma unroll
        for (int mi = 0; mi < 4; mi++)
            LDSM4(f[mi][0], f[mi][1], f[mi][2], f[mi][3],
                  a0 + mi * (16 * APAD * 4));
    };
    auto ldb = [&](uint32_t bAddr, int js, uint32_t f[8][2]) {
        const uint32_t b0 = bAddr + js * 32;
#pragma unroll
        for (int jb = 0; jb < 4; jb++)
            LDSM4(f[2 * jb][0], f[2 * jb][1], f[2 * jb + 1][0], f[2 * jb + 1][1],
                  b0 + jb * (16 * BNPAD * 4));
    };

    // prologue: tiles 0,1 issued; tile 0 strictly drained+published; preload js0
    load_tile(0, 0); cp_commit();
    load_tile(1, 1); cp_commit();
    cp_wait<1>();          // pending {0,1} -> tile 0 done (tile 1 may fly)
    __syncthreads();       // tile 0 published to all warps
    lda(smem_base + aOff, 0, af[0]);
    ldb(smem_base + bOff, 0, bf[0]);

    int s_cur = 0;
#pragma unroll 1
    for (int kt = 0; kt < KTILES; ++kt) {
        const int s_next = (s_cur == STAGES - 1) ? 0 : s_cur + 1;
        const int s_load = (s_next == STAGES - 1) ? 0 : s_next + 1;

        // STRICT handoff: sole pending group here is tile kt+1 (kt+2 not yet
        // committed) -> wait<0> == drain tile kt+1 exactly. The barrier then
        // (a) publishes tile kt+1 to all warps and (b) separates last iter's
        // readers of stage s_load from the overwrite below.
        cp_wait<0>();
        __syncthreads();
        if (kt + 2 < KTILES) load_tile(kt + 2, s_load);
        cp_commit();

        const uint32_t stgC = smem_base + s_cur * (STAGE_FLOATS * 4);
        const uint32_t stgN = smem_base + s_next * (STAGE_FLOATS * 4);

#pragma unroll
        for (int js = 0; js < 4; ++js) {
            const int cur = js & 1;
            if (js < 3) {
                lda(stgC + aOff, js + 1, af[cur ^ 1]);
                ldb(stgC + bOff, js + 1, bf[cur ^ 1]);
            } else if (kt + 1 < KTILES) {
                // cross-tile prefetch: tile kt+1 drained+published at iter top
                lda(stgN + aOff, 0, af[cur ^ 1]);
                ldb(stgN + bOff, 0, bf[cur ^ 1]);
            }
#pragma unroll
            for (int mi = 0; mi < 4; mi++)
#pragma unroll
                for (int nj = 0; nj < 8; nj++)
                    mma_tf32(cacc[mi][nj], af[cur][mi], bf[cur][nj], cacc[mi][nj]);
        }

        s_cur = s_next;
    }

    // ---- epilogue: x = acc + q[b][n]; contrib = tanh(x)*v[n]; row-reduce ----
    float qv[8][2], vv[8][2];
#pragma unroll
    for (int nj = 0; nj < 8; nj++)
#pragma unroll
        for (int cc = 0; cc < 2; cc++) {
            int n = bn0 + wn * 64 + nj * 8 + 2 * tg + cc;
            qv[nj][cc] = g_q[batch * E_ + n];
            vv[nj][cc] = v[n];
        }

    __syncthreads();
    float* red = smem;
    if (tid < 128) red[tid] = 0.f;
    __syncthreads();

#pragma unroll
    for (int mi = 0; mi < 4; mi++)
#pragma unroll
        for (int h = 0; h < 2; h++) {
            float s = 0.f;
#pragma unroll
            for (int nj = 0; nj < 8; nj++)
#pragma unroll
                for (int cc = 0; cc < 2; cc++) {
                    float x = cacc[mi][nj][h * 2 + cc] + qv[nj][cc];
                    s = fmaf(tanh_fast(x), vv[nj][cc], s);
                }
            s += __shfl_xor_sync(0xffffffffu, s, 1);
            s += __shfl_xor_sync(0xffffffffu, s, 2);
            if (tg == 0) atomicAdd(&red[wm * 64 + mi * 16 + h * 8 + g], s);
        }
    __syncthreads();
    if (tid < 128) atomicAdd(&g_scores[m0 + tid], red[tid]);
}

// ---------------- kernel 4: per-batch softmax over S ----------------
__global__ void softmax_kernel() {
    __shared__ float sred[256];
    const int b = blockIdx.x, tid = threadIdx.x;
    const float* sc = g_scores + b * S_;

    float m = -1e30f;
    for (int i = tid; i < S_; i += 256) m = fmaxf(m, sc[i]);
    sred[tid] = m;
    __syncthreads();
    for (int o = 128; o > 0; o >>= 1) {
        if (tid < o) sred[tid] = fmaxf(sred[tid], sred[tid + o]);
        __syncthreads();
    }
    m = sred[0];
    __syncthreads();

    float sum = 0.f;
    for (int i = tid; i < S_; i += 256) {
        float e = expf(sc[i] - m);
        g_attn[b * S_ + i] = e;
        sum += e;
    }
    sred[tid] = sum;
    __syncthreads();
    for (int o = 128; o > 0; o >>= 1) {
        if (tid < o) sred[tid] += sred[tid + o];
        __syncthreads();
    }
    const float inv = 1.f / sred[0];
    for (int i = tid; i < S_; i += 256) g_attn[b * S_ + i] *= inv;
}

// ---------------- kernel 5: context[b][e] = sum_s attn*enc ----------------
// 32 s-chunks of 64 rows (1024 blocks) for higher resident-thread count on
// this DRAM-latency-bound reduction.
__global__ void context_kernel(const float* __restrict__ enc,
                               float* __restrict__ out) {
    __shared__ float a[64];
    const int b = blockIdx.y, s0 = blockIdx.x * 64, tid = threadIdx.x;
    if (tid < 64) a[tid] = g_attn[b * S_ + s0 + tid];
    __syncthreads();

    const float4* e4 =
        reinterpret_cast<const float4*>(enc + ((size_t)b * S_ + s0) * E_) + tid;
    float4 acc = make_float4(0.f, 0.f, 0.f, 0.f);
#pragma unroll 4
    for (int s = 0; s < 64; s++) {
        float4 x = e4[(size_t)s * (E_ / 4)];
        float w = a[s];
        acc.x += w * x.x;
        acc.y += w * x.y;
        acc.z += w * x.z;
        acc.w += w * x.w;
    }
    float* o = out + b * E_ + tid * 4;
    atomicAdd(o + 0, acc.x);
    atomicAdd(o + 1, acc.y);
    atomicAdd(o + 2, acc.z);
    atomicAdd(o + 3, acc.w);
}

// ---------------- launch ----------------
extern "C" void kernel_launch(void* const* d_in, const int* in_sizes, int n_in,
                              void* d_out, int out_size) {
    const float* enc = (const float*)d_in[0];  // [32,2048,1024]
    const float* dec = (const float*)d_in[1];  // [32,1,1024]
    const float* w1  = (const float*)d_in[2];  // [1024,1024]
    const float* b1  = (const float*)d_in[3];  // [1024]
    const float* w2  = (const float*)d_in[4];  // [1024,1024]
    const float* b2  = (const float*)d_in[5];  // [1024]
    const float* v   = (const float*)d_in[6];  // [1024,1]
    // d_in[7] = bv: softmax shift-invariant, never affects output
    float* out = (float*)d_out;                // [32,1024]

    cudaFuncSetAttribute(score_gemm_kernel,
                         cudaFuncAttributeMaxDynamicSharedMemorySize, GEMM_SMEM);

    init_kernel<<<256, 256>>>(b1, b2, out);
    transpose_w1_kernel<<<dim3(32, 32), dim3(32, 8)>>>(w1);
    qproj_kernel<<<dim3(8, 8), 128>>>(dec, w2);
    score_gemm_kernel<<<dim3(E_ / BN, MTOT / BM), 128, GEMM_SMEM>>>(enc, v);
    softmax_kernel<<<32, 256>>>();
    context_kernel<<<dim3(32, 32), 256>>>(enc, out);
}

// round 17
// speedup vs baseline: 1.0805x; 1.0805x over previous
#include <cuda_runtime.h>
#include <cstdint>
#include <cstddef>

#define B_   32
#define S_   2048
#define E_   1024
#define MTOT (B_ * S_)

// ---------------- scratch (no allocations allowed) ----------------
__device__ float g_scores[MTOT];
__device__ float g_attn[MTOT];
__device__ float g_q[B_ * E_];
__device__ float g_w1t[E_ * E_];   // w1 transposed [n][k], tf32-pre-rounded bits

// ---------------- helpers ----------------
__device__ __forceinline__ uint32_t f2tf32(float x) {
    uint32_t r;
    asm("cvt.rna.tf32.f32 %0, %1;" : "=r"(r) : "f"(x));
    return r;
}

__device__ __forceinline__ void mma_tf32(float d[4], const uint32_t a[4],
                                         const uint32_t b[2], const float c[4]) {
    asm volatile(
        "mma.sync.aligned.m16n8k8.row.col.f32.tf32.tf32.f32 "
        "{%0,%1,%2,%3},{%4,%5,%6,%7},{%8,%9},{%10,%11,%12,%13};\n"
        : "=f"(d[0]), "=f"(d[1]), "=f"(d[2]), "=f"(d[3])
        : "r"(a[0]), "r"(a[1]), "r"(a[2]), "r"(a[3]),
          "r"(b[0]), "r"(b[1]),
          "f"(c[0]), "f"(c[1]), "f"(c[2]), "f"(c[3]));
}

// ldmatrix x4: four 8x8 b16 matrices -> one reg each (tf32 fragment trick).
#define LDSM4(r0, r1, r2, r3, addr)                                          \
    asm volatile("ldmatrix.sync.aligned.m8n8.x4.shared.b16 {%0,%1,%2,%3}, [%4];" \
        : "=r"(r0), "=r"(r1), "=r"(r2), "=r"(r3) : "r"(addr))

__device__ __forceinline__ void cp16(uint32_t s, const void* g) {
    asm volatile("cp.async.cg.shared.global [%0],[%1],16;\n" :: "r"(s), "l"(g));
}
__device__ __forceinline__ void cp_commit() { asm volatile("cp.async.commit_group;\n"); }
template <int N>
__device__ __forceinline__ void cp_wait() { asm volatile("cp.async.wait_group %0;\n" ::"n"(N)); }

__device__ __forceinline__ float tanh_fast(float x) {
    float r;
    asm("tanh.approx.f32 %0, %1;" : "=f"(r) : "f"(x));
    return r;
}

// ---------------- kernel 1: init scratch + output ----------------
__global__ void init_kernel(const float* __restrict__ b1,
                            const float* __restrict__ b2,
                            float* __restrict__ out) {
    int i = blockIdx.x * blockDim.x + threadIdx.x;
    if (i < MTOT) g_scores[i] = 0.f;
    if (i < B_ * E_) {
        g_q[i] = b1[i & (E_ - 1)] + b2[i & (E_ - 1)];
        out[i] = 0.f;
    }
}

// ---------------- kernel 1b: transpose w1 -> g_w1t[n][k], tf32-rounded ----
__global__ void transpose_w1_kernel(const float* __restrict__ w1) {
    __shared__ float t[32][33];
    const int x = threadIdx.x, y = threadIdx.y;
    const int bx = blockIdx.x * 32, by = blockIdx.y * 32;
#pragma unroll
    for (int i = 0; i < 32; i += 8) t[y + i][x] = w1[(size_t)(by + y + i) * E_ + bx + x];
    __syncthreads();
#pragma unroll
    for (int i = 0; i < 32; i += 8)
        g_w1t[(size_t)(bx + y + i) * E_ + by + x] = __uint_as_float(f2tf32(t[x][y + i]));
}

// ---------------- kernel 2: q[b][e] += dec[b]·w2[:,e] ----------------
__global__ void qproj_kernel(const float* __restrict__ dec,
                             const float* __restrict__ w2) {
    __shared__ float sdec[32 * 128];
    const int tid = threadIdx.x;
    const int e   = blockIdx.x * 128 + tid;
    const int d0  = blockIdx.y * 128;

    for (int i = tid; i < 32 * 128; i += 128) {
        int b = i >> 7, d = i & 127;
        sdec[i] = dec[b * E_ + d0 + d];
    }
    __syncthreads();

    float acc[32];
#pragma unroll
    for (int b = 0; b < 32; b++) acc[b] = 0.f;
    for (int d = 0; d < 128; ++d) {
        float w = w2[(size_t)(d0 + d) * E_ + e];
#pragma unroll
        for (int b = 0; b < 32; b++) acc[b] += sdec[b * 128 + d] * w;
    }
#pragma unroll
    for (int b = 0; b < 32; b++) atomicAdd(&g_q[b * E_ + e], acc[b]);
}

// ---------------- kernel 3: score GEMM + tanh/v epilogue ----------------
// scores[m] += sum_n tanh( (enc@w1)[m,n] + q[b][n] ) * v[n]
// BM=128 BN=128 BK=32, 3-stage cp.async, 128 thr (4 warps 2x2),
// warp tile 64x64, ldmatrix, fragment double-buffering + cross-tile js0
// prefetch. STRICT pipeline, wait placed pre-js3 for max slack:
//   iter kt:  load(kt+2) [stage freed by iter kt-1's sync]; commit;
//             js0..js2;  cp_wait<1> [drains kt+1: 1.75-iter slack];
//             __syncthreads [publishes kt+1 + releases stage(kt) for kt+1's
//             load(kt+3)];  js3 [cross-prefetch kt+1's js0 frags].
// Commit is UNCONDITIONAL every iter so wait<1>'s "most recent group"
// accounting stays invariant through the tail (empty groups).
// A: raw fp32 (HW tf32 truncation); B: pre-rounded rna. 2 CTAs/SM.
#define BM   128
#define BN   128
#define BK   32
#define STAGES 3
#define KTILES (E_ / BK)
#define APAD 36
#define BNPAD 36
#define A_FLOATS (BM * APAD)               // 4608
#define B_FLOATS (BN * BNPAD)              // 4608
#define STAGE_FLOATS (A_FLOATS + B_FLOATS) // 9216
#define GEMM_SMEM (STAGES * STAGE_FLOATS * 4)   // 110592 B

__global__ __launch_bounds__(128, 2) void score_gemm_kernel(
    const float* __restrict__ enc, const float* __restrict__ v) {
    extern __shared__ float smem[];

    const int tid   = threadIdx.x;
    const int bn0   = blockIdx.x * BN;
    const int m0    = blockIdx.y * BM;
    const int batch = m0 / S_;   // BM divides S_

    const int warp = tid >> 5, lane = tid & 31;
    const int wm = warp >> 1, wn = warp & 1;   // 2x2 warp grid, 64x64 tiles
    const int g = lane >> 2, tg = lane & 3;
    const int q8 = lane >> 3, rr = lane & 7;   // ldmatrix lane mapping

    float cacc[4][8][4];
#pragma unroll
    for (int i = 0; i < 4; i++)
#pragma unroll
        for (int j = 0; j < 8; j++)
#pragma unroll
            for (int r = 0; r < 4; r++) cacc[i][j][r] = 0.f;

    const uint32_t smem_base = (uint32_t)__cvta_generic_to_shared(smem);
    // A matrices: rows {R+rr, R+8+rr} x k-halves {k0, k0+4}
    const uint32_t aOff = ((wm * 64 + (q8 & 1) * 8 + rr) * APAD + (q8 >> 1) * 4) * 4;
    // B matrices: n-rows {n0+rr, n0+8+rr} x k-halves {k0, k0+4}
    const uint32_t bOff = (uint32_t)(A_FLOATS * 4) +
                          ((wn * 64 + (q8 >> 1) * 8 + rr) * BNPAD + (q8 & 1) * 4) * 4;

    auto load_tile = [&](int kt, int s) {
        float* A  = smem + s * STAGE_FLOATS;
        float* Bn = A + A_FLOATS;          // layout [n][k], stride BNPAD
        const int kc = kt * BK;
#pragma unroll
        for (int i = 0; i < 8; i++) {      // A: 128 m-rows x 32 k floats
            int u = tid + 128 * i;
            int row = u >> 3, cu = (u & 7) << 2;
            cp16((uint32_t)__cvta_generic_to_shared(A + row * APAD + cu),
                 enc + (size_t)(m0 + row) * E_ + kc + cu);
        }
#pragma unroll
        for (int i = 0; i < 8; i++) {      // B: 128 n-rows x 32 k floats
            int u = tid + 128 * i;
            int row = u >> 3, cu = (u & 7) << 2;
            cp16((uint32_t)__cvta_generic_to_shared(Bn + row * BNPAD + cu),
                 g_w1t + (size_t)(bn0 + row) * E_ + kc + cu);
        }
    };

    uint32_t af[2][4][4], bf[2][8][2];
    auto lda = [&](uint32_t aAddr, int js, uint32_t f[4][4]) {
        const uint32_t a0 = aAddr + js * 32;
#pragma unroll
        for (int mi = 0; mi < 4; mi++)
            LDSM4(f[mi][0], f[mi][1], f[mi][2], f[mi][3],
                  a0 + mi * (16 * APAD * 4));
    };
    auto ldb = [&](uint32_t bAddr, int js, uint32_t f[8][2]) {
        const uint32_t b0 = bAddr + js * 32;
#pragma unroll
        for (int jb = 0; jb < 4; jb++)
            LDSM4(f[2 * jb][0], f[2 * jb][1], f[2 * jb + 1][0], f[2 * jb + 1][1],
                  b0 + jb * (16 * BNPAD * 4));
    };

    // prologue: tiles 0,1 issued; tile 0 strictly drained+published; preload js0
    load_tile(0, 0); cp_commit();
    load_tile(1, 1); cp_commit();
    cp_wait<1>();          // pending {0,1} -> drains tile 0 (1 may fly)
    __syncthreads();       // tile 0 published to all warps
    lda(smem_base + aOff, 0, af[0]);
    ldb(smem_base + bOff, 0, bf[0]);

    int s_cur = 0;
#pragma unroll 1
    for (int kt = 0; kt < KTILES; ++kt) {
        const int s_next = (s_cur == STAGES - 1) ? 0 : s_cur + 1;
        const int s_load = (s_next == STAGES - 1) ? 0 : s_next + 1;

        // stage s_load's readers (tile kt-1 frags) finished before iter kt-1's
        // pre-js3 sync -> safe to overwrite now, no wait needed here.
        if (kt + 2 < KTILES) load_tile(kt + 2, s_load);
        cp_commit();       // unconditional: keeps wait<1> group accounting fixed

        const uint32_t stgC = smem_base + s_cur * (STAGE_FLOATS * 4);
        const uint32_t stgN = smem_base + s_next * (STAGE_FLOATS * 4);

#pragma unroll
        for (int js = 0; js < 3; ++js) {
            const int cur = js & 1;
            lda(stgC + aOff, js + 1, af[cur ^ 1]);
            ldb(stgC + bOff, js + 1, bf[cur ^ 1]);
#pragma unroll
            for (int mi = 0; mi < 4; mi++)
#pragma unroll
                for (int nj = 0; nj < 8; nj++)
                    mma_tf32(cacc[mi][nj], af[cur][mi], bf[cur][nj], cacc[mi][nj]);
        }

        // STRICT drain of tile kt+1 (committed iter kt-1 top: ~1.75-iter slack)
        // + publish; sync also separates this iter's stage-s_cur reads (done at
        // js=2 above) from next iter's load(kt+3) overwrite of that stage.
        cp_wait<1>();
        __syncthreads();

        {   // js = 3
            if (kt + 1 < KTILES) {
                lda(stgN + aOff, 0, af[0]);   // cross-tile prefetch: kt+1 js0
                ldb(stgN + bOff, 0, bf[0]);
            }
#pragma unroll
            for (int mi = 0; mi < 4; mi++)
#pragma unroll
                for (int nj = 0; nj < 8; nj++)
                    mma_tf32(cacc[mi][nj], af[1][mi], bf[1][nj], cacc[mi][nj]);
        }

        s_cur = s_next;
    }

    // ---- epilogue: x = acc + q[b][n]; contrib = tanh(x)*v[n]; row-reduce ----
    float qv[8][2], vv[8][2];
#pragma unroll
    for (int nj = 0; nj < 8; nj++)
#pragma unroll
        for (int cc = 0; cc < 2; cc++) {
            int n = bn0 + wn * 64 + nj * 8 + 2 * tg + cc;
            qv[nj][cc] = g_q[batch * E_ + n];
            vv[nj][cc] = v[n];
        }

    __syncthreads();
    float* red = smem;
    if (tid < 128) red[tid] = 0.f;
    __syncthreads();

#pragma unroll
    for (int mi = 0; mi < 4; mi++)
#pragma unroll
        for (int h = 0; h < 2; h++) {
            float s = 0.f;
#pragma unroll
            for (int nj = 0; nj < 8; nj++)
#pragma unroll
                for (int cc = 0; cc < 2; cc++) {
                    float x = cacc[mi][nj][h * 2 + cc] + qv[nj][cc];
                    s = fmaf(tanh_fast(x), vv[nj][cc], s);
                }
            s += __shfl_xor_sync(0xffffffffu, s, 1);
            s += __shfl_xor_sync(0xffffffffu, s, 2);
            if (tg == 0) atomicAdd(&red[wm * 64 + mi * 16 + h * 8 + g], s);
        }
    __syncthreads();
    if (tid < 128) atomicAdd(&g_scores[m0 + tid], red[tid]);
}

// ---------------- kernel 4: per-batch softmax over S ----------------
__global__ void softmax_kernel() {
    __shared__ float sred[256];
    const int b = blockIdx.x, tid = threadIdx.x;
    const float* sc = g_scores + b * S_;

    float m = -1e30f;
    for (int i = tid; i < S_; i += 256) m = fmaxf(m, sc[i]);
    sred[tid] = m;
    __syncthreads();
    for (int o = 128; o > 0; o >>= 1) {
        if (tid < o) sred[tid] = fmaxf(sred[tid], sred[tid + o]);
        __syncthreads();
    }
    m = sred[0];
    __syncthreads();

    float sum = 0.f;
    for (int i = tid; i < S_; i += 256) {
        float e = expf(sc[i] - m);
        g_attn[b * S_ + i] = e;
        sum += e;
    }
    sred[tid] = sum;
    __syncthreads();
    for (int o = 128; o > 0; o >>= 1) {
        if (tid < o) sred[tid] += sred[tid + o];
        __syncthreads();
    }
    const float inv = 1.f / sred[0];
    for (int i = tid; i < S_; i += 256) g_attn[b * S_ + i] *= inv;
}

// ---------------- kernel 5: context[b][e] = sum_s attn*enc ----------------
__global__ void context_kernel(const float* __restrict__ enc,
                               float* __restrict__ out) {
    __shared__ float a[64];
    const int b = blockIdx.y, s0 = blockIdx.x * 64, tid = threadIdx.x;
    if (tid < 64) a[tid] = g_attn[b * S_ + s0 + tid];
    __syncthreads();

    const float4* e4 =
        reinterpret_cast<const float4*>(enc + ((size_t)b * S_ + s0) * E_) + tid;
    float4 acc = make_float4(0.f, 0.f, 0.f, 0.f);
#pragma unroll 4
    for (int s = 0; s < 64; s++) {
        float4 x = e4[(size_t)s * (E_ / 4)];
        float w = a[s];
        acc.x += w * x.x;
        acc.y += w * x.y;
        acc.z += w * x.z;
        acc.w += w * x.w;
    }
    float* o = out + b * E_ + tid * 4;
    atomicAdd(o + 0, acc.x);
    atomicAdd(o + 1, acc.y);
    atomicAdd(o + 2, acc.z);
    atomicAdd(o + 3, acc.w);
}

// ---------------- launch ----------------
extern "C" void kernel_launch(void* const* d_in, const int* in_sizes, int n_in,
                              void* d_out, int out_size) {
    const float* enc = (const float*)d_in[0];  // [32,2048,1024]
    const float* dec = (const float*)d_in[1];  // [32,1,1024]
    const float* w1  = (const float*)d_in[2];  // [1024,1024]
    const float* b1  = (const float*)d_in[3];  // [1024]
    const float* w2  = (const float*)d_in[4];  // [1024,1024]
    const float* b2  = (const float*)d_in[5];  // [1024]
    const float* v   = (const float*)d_in[6];  // [1024,1]
    // d_in[7] = bv: softmax shift-invariant, never affects output
    float* out = (float*)d_out;                // [32,1024]

    cudaFuncSetAttribute(score_gemm_kernel,
                         cudaFuncAttributeMaxDynamicSharedMemorySize, GEMM_SMEM);

    init_kernel<<<256, 256>>>(b1, b2, out);
    transpose_w1_kernel<<<dim3(32, 32), dim3(32, 8)>>>(w1);
    qproj_kernel<<<dim3(8, 8), 128>>>(dec, w2);
    score_gemm_kernel<<<dim3(E_ / BN, MTOT / BM), 128, GEMM_SMEM>>>(enc, v);
    softmax_kernel<<<32, 256>>>();
    context_kernel<<<dim3(32, 32), 256>>>(enc, out);
}